// round 1
// baseline (speedup 1.0000x reference)
#include <cuda_runtime.h>
#include <math.h>

#define DM 128
#define NN 65536

// activations scratch: h and c per node (allowed: __device__ globals, no malloc)
__device__ float g_h[NN * DM];
__device__ float g_c[NN * DM];

__device__ __forceinline__ float sigf(float x) { return 1.0f / (1.0f + expf(-x)); }

// ---------------------------------------------------------------------------
// Leaves: embed + norm-clip. One warp per node. Also scatter into output.
// ---------------------------------------------------------------------------
__global__ void leaf_kernel(const int* __restrict__ tokens,
                            const float* __restrict__ emb,
                            float* __restrict__ out) {
    int n = blockIdx.x * 8 + (threadIdx.x >> 5);   // node 0..32767
    int lane = threadIdx.x & 31;
    int tok = tokens[n];
    float4 e = ((const float4*)emb)[tok * 32 + lane];
    float ss = e.x * e.x + e.y * e.y + e.z * e.z + e.w * e.w;
#pragma unroll
    for (int o = 16; o; o >>= 1) ss += __shfl_xor_sync(0xffffffffu, ss, o);
    float nrm = sqrtf(ss);
    // min(1, 1/max(nrm,1e-7)) == (nrm > 1 ? 1/nrm : 1)
    float s = nrm > 1.0f ? 1.0f / nrm : 1.0f;
    float4 h = make_float4(e.x * s, e.y * s, e.z * s, e.w * s);
    ((float4*)g_h)[n * 32 + lane] = h;
    ((float4*)g_c)[n * 32 + lane] = make_float4(0.f, 0.f, 0.f, 0.f);
    int b = n >> 9, j = n & 511;                    // level 0: C=512, off=0
    ((float4*)out)[(b * 1024 + j) * 32 + lane] = h;
}

// ---------------------------------------------------------------------------
// Binary level: per block, 32 nodes x 640 gate outputs, K=256 (concat h_l,h_r)
// fused GEMM + LSTM gates + output scatter.
// Thread map: 256 threads = (tx:32 in N) x (ty:8 in M). Each thread:
//   4 M-rows (ty*4+i), 5 gates x 4 dims (cols q*128 + tx*4 + j) -> 80 accs.
// ---------------------------------------------------------------------------
__global__ __launch_bounds__(256) void bin_kernel(
    const int* __restrict__ left, const int* __restrict__ right,
    const float* __restrict__ Wb, const float* __restrict__ bb,
    int s, int C, int offl, float* __restrict__ out) {
    __shared__ float Ws[8 * 640];   // K-chunk 8 x 640 cols (20 KB)
    __shared__ float xs[8 * 32];    // K-chunk 8 x 32 nodes
    __shared__ int sli[32], sri[32];

    int t = threadIdx.x;
    int tx = t & 31, ty = t >> 5;
    int m0 = blockIdx.x * 32;

    if (t < 32) {
        sli[t] = left[s + m0 + t];
        sri[t] = right[s + m0 + t];
    }
    __syncthreads();

    float acc[4][20];
#pragma unroll
    for (int i = 0; i < 4; i++)
#pragma unroll
        for (int c = 0; c < 20; c++) acc[i][c] = 0.f;

    int lm = t >> 3, lkk = t & 7;  // loading map: node lm, k-sub lkk (coalesced 32B/node)
    float4* Ws4 = (float4*)Ws;
    float4* xs4 = (float4*)xs;

    for (int kc = 0; kc < 32; kc++) {
        __syncthreads();
        // W chunk: rows kc*8..kc*8+7 (contiguous 5120 floats), 5 float4/thread
        const float4* W4 = (const float4*)(Wb + kc * 8 * 640);
#pragma unroll
        for (int r = 0; r < 5; r++) Ws4[t + 256 * r] = W4[t + 256 * r];
        // x chunk: x[m][k] = k<128 ? h[left[m]][k] : h[right[m]][k-128]
        int k = kc * 8 + lkk;
        int src = (k < 128) ? sli[lm] : sri[lm];
        xs[lkk * 32 + lm] = g_h[src * DM + (k & 127)];
        __syncthreads();

#pragma unroll
        for (int k2 = 0; k2 < 8; k2++) {
            float4 wv[5];
#pragma unroll
            for (int q = 0; q < 5; q++) wv[q] = Ws4[k2 * 160 + q * 32 + tx];
            float4 xv = xs4[k2 * 8 + ty];  // 4 M-rows' x at this k
            float xa[4] = {xv.x, xv.y, xv.z, xv.w};
#pragma unroll
            for (int i = 0; i < 4; i++) {
#pragma unroll
                for (int q = 0; q < 5; q++) {
                    acc[i][q * 4 + 0] += xa[i] * wv[q].x;
                    acc[i][q * 4 + 1] += xa[i] * wv[q].y;
                    acc[i][q * 4 + 2] += xa[i] * wv[q].z;
                    acc[i][q * 4 + 3] += xa[i] * wv[q].w;
                }
            }
        }
    }

    // Epilogue: bias + gates + cell update + scatter
    int d0 = tx * 4;
    float4 bias[5];
#pragma unroll
    for (int q = 0; q < 5; q++) bias[q] = *(const float4*)(bb + q * 128 + d0);

#pragma unroll
    for (int i = 0; i < 4; i++) {
        int mi = ty * 4 + i;
        int n = s + m0 + mi;
        int li = sli[mi], ri = sri[mi];
        float4 cl = *(const float4*)(g_c + li * DM + d0);
        float4 cr = *(const float4*)(g_c + ri * DM + d0);
        float* clp = (float*)&cl;
        float* crp = (float*)&cr;
        float4 hv, cv;
        float* hp = (float*)&hv;
        float* cp = (float*)&cv;
#pragma unroll
        for (int j = 0; j < 4; j++) {
            float gi = acc[i][0 * 4 + j] + ((float*)&bias[0])[j];
            float go = acc[i][1 * 4 + j] + ((float*)&bias[1])[j];
            float gu = acc[i][2 * 4 + j] + ((float*)&bias[2])[j];
            float gl = acc[i][3 * 4 + j] + ((float*)&bias[3])[j];
            float gr = acc[i][4 * 4 + j] + ((float*)&bias[4])[j];
            float c = sigf(gi) * tanhf(gu) + sigf(gl) * clp[j] + sigf(gr) * crp[j];
            float h = sigf(go) * tanhf(c);
            cp[j] = c;
            hp[j] = h;
        }
        *(float4*)(g_h + n * DM + d0) = hv;
        *(float4*)(g_c + n * DM + d0) = cv;
        int local = m0 + mi;
        int b = local / C, jj = local % C;
        *(float4*)(out + ((long long)(b * 1024 + offl + jj)) * DM + d0) = hv;
    }
}

// ---------------------------------------------------------------------------
// Unary top level: 64 nodes, K=128, N=512. One block (128 threads) per node.
// ---------------------------------------------------------------------------
__global__ void unary_kernel(const int* __restrict__ left,
                             const float* __restrict__ Wu,
                             const float* __restrict__ bu,
                             float* __restrict__ out) {
    __shared__ float xh[128];
    int n = 65472 + blockIdx.x;
    int tx = threadIdx.x;
    int ch = left[n];
    xh[tx] = g_h[ch * DM + tx];
    __syncthreads();
    float acc[4] = {0.f, 0.f, 0.f, 0.f};
    for (int k = 0; k < 128; k++) {
        float x = xh[k];
#pragma unroll
        for (int q = 0; q < 4; q++) acc[q] += x * Wu[k * 512 + q * 128 + tx];
    }
    float cc = g_c[ch * DM + tx];
    float gi = acc[0] + bu[tx];
    float go = acc[1] + bu[128 + tx];
    float gu = acc[2] + bu[256 + tx];
    float gf = acc[3] + bu[384 + tx];
    float c = sigf(gi) * tanhf(gu) + sigf(gf) * cc;
    float h = sigf(go) * tanhf(c);
    // level 10: C=1, off=1023
    out[((long long)(blockIdx.x * 1024 + 1023)) * DM + tx] = h;
}

// ---------------------------------------------------------------------------
// Launch: leaves, 9 binary levels, unary top. All on default stream
// (graph-capturable: kernels only, no sync/alloc).
// ---------------------------------------------------------------------------
extern "C" void kernel_launch(void* const* d_in, const int* in_sizes, int n_in,
                              void* d_out, int out_size) {
    const int* tokens = (const int*)d_in[0];
    const int* left   = (const int*)d_in[1];
    const int* right  = (const int*)d_in[2];
    const float* emb  = (const float*)d_in[3];
    const float* Wu   = (const float*)d_in[4];
    const float* bu   = (const float*)d_in[5];
    const float* Wb   = (const float*)d_in[6];
    const float* bb   = (const float*)d_in[7];
    float* out = (float*)d_out;

    static const int Gh[12]  = {0, 32768, 49152, 57344, 61440, 63488,
                                64512, 65024, 65280, 65408, 65472, 65536};
    static const int Ch[11]  = {512, 256, 128, 64, 32, 16, 8, 4, 2, 1, 1};
    static const int Off[11] = {0, 512, 768, 896, 960, 992, 1008, 1016, 1020, 1022, 1023};

    leaf_kernel<<<4096, 256>>>(tokens, emb, out);
    for (int l = 1; l <= 9; l++) {
        int M = 64 * Ch[l];
        bin_kernel<<<M / 32, 256>>>(left, right, Wb, bb, Gh[l], Ch[l], Off[l], out);
    }
    unary_kernel<<<64, 128>>>(left, Wu, bu, out);
}

// round 5
// speedup vs baseline: 2.0897x; 2.0897x over previous
#include <cuda_runtime.h>
#include <cuda_bf16.h>
#include <math.h>
#include <cstdint>

#define DM 128
#define NN 65536

// ---------------- device scratch (module globals; no runtime alloc) --------
__device__ float          g_c [NN * DM];     // cell state fp32
__device__ __nv_bfloat16  g_hh[NN * DM];     // h hi bf16 (plain [node][k])
__device__ __nv_bfloat16  g_hl[NN * DM];     // h lo bf16 (h = hh + hl)
__device__ __nv_bfloat16  g_wth[640 * 256];  // W_bin^T hi [n][k'] (k 16-block permuted)
__device__ __nv_bfloat16  g_wtl[640 * 256];  // W_bin^T lo, same layout

__device__ __forceinline__ float sigf(float x) { return 1.0f / (1.0f + expf(-x)); }

// mma.sync m16n8k16 bf16 -> f32 (arch-neutral PTX, runs on tensor pipe)
#define MMA(acc, a, b0, b1)                                                     \
    asm volatile("mma.sync.aligned.m16n8k16.row.col.f32.bf16.bf16.f32 "         \
                 "{%0,%1,%2,%3}, {%4,%5,%6,%7}, {%8,%9}, {%0,%1,%2,%3};"        \
                 : "+f"((acc)[0]), "+f"((acc)[1]), "+f"((acc)[2]), "+f"((acc)[3]) \
                 : "r"((a)[0]), "r"((a)[1]), "r"((a)[2]), "r"((a)[3]),          \
                   "r"(b0), "r"(b1))

// ---------------- SMEM layout (bin_mma): 8-dim N-tile -> fits 48KB ----------
#define SB_H      264                      // halves per B smem row (256 + 8 pad)
#define SB_B      (SB_H * 2)               // 528 bytes
#define SM_SLI    0
#define SM_SRI    512
#define SM_BHI    1024
#define SM_BLO    (1024 + 40 * SB_B)       // 22144
#define SMEM_TOT  (SM_BLO + 40 * SB_B)     // 43264  (< 48KB, no attribute needed)

// ---------------------------------------------------------------------------
// prep: split + transpose W_bin [256,640] -> WT hi/lo [640][256'] where k' is
// permuted per 16-block so each mma B-fragment (b0,b1) is one 8-byte read:
// order k0,k1,k8,k9, k2,k3,k10,k11, k4,k5,k12,k13, k6,k7,k14,k15
// ---------------------------------------------------------------------------
__global__ void prep_w(const float* __restrict__ Wb) {
    int i = blockIdx.x * 256 + threadIdx.x;   // 163840 total
    int k = i / 640, n = i % 640;
    float w = Wb[i];
    __nv_bfloat16 hi = __float2bfloat16(w);
    float lo = w - __bfloat162float(hi);
    int ks = k >> 4, kk = k & 15;
    int j = (kk & 7) >> 1, e = kk & 1;
    int pos = (kk < 8) ? (j * 4 + e) : (j * 4 + 2 + e);
    int dst = n * 256 + ks * 16 + pos;
    g_wth[dst] = hi;
    g_wtl[dst] = __float2bfloat16(lo);
}

// ---------------------------------------------------------------------------
// leaves: embed + norm clip, write h hi/lo, c=0, scatter output
// ---------------------------------------------------------------------------
__global__ void leaf_kernel(const int* __restrict__ tokens,
                            const float* __restrict__ emb,
                            float* __restrict__ out) {
    int n = blockIdx.x * 8 + (threadIdx.x >> 5);
    int lane = threadIdx.x & 31;
    int tok = tokens[n];
    float4 e = ((const float4*)emb)[tok * 32 + lane];
    float ss = e.x * e.x + e.y * e.y + e.z * e.z + e.w * e.w;
#pragma unroll
    for (int o = 16; o; o >>= 1) ss += __shfl_xor_sync(0xffffffffu, ss, o);
    float nrm = sqrtf(ss);
    float s = nrm > 1.0f ? 1.0f / nrm : 1.0f;
    float hv[4] = {e.x * s, e.y * s, e.z * s, e.w * s};
#pragma unroll
    for (int c = 0; c < 4; c++) {
        __nv_bfloat16 hi = __float2bfloat16(hv[c]);
        float lo = hv[c] - __bfloat162float(hi);
        g_hh[n * DM + lane * 4 + c] = hi;
        g_hl[n * DM + lane * 4 + c] = __float2bfloat16(lo);
    }
    ((float4*)g_c)[n * 32 + lane] = make_float4(0.f, 0.f, 0.f, 0.f);
    int b = n >> 9, j = n & 511;
    ((float4*)out)[(b * 1024 + j) * 32 + lane] = make_float4(hv[0], hv[1], hv[2], hv[3]);
}

// ---------------------------------------------------------------------------
// binary level: CTA = up-to-128 nodes x (5 gates x 8 dims); 4 warps, each m32.
// GEMM [128 x 256] @ [256 x 40] via mma.sync bf16, 3-term precision split.
// A fragments from global (L1/L2-resident, 16x reuse across grid.y),
// B fragments from padded smem (conflict-free uint2 reads).
// ---------------------------------------------------------------------------
__global__ void __launch_bounds__(128)
bin_mma(const int* __restrict__ left, const int* __restrict__ right,
        const float* __restrict__ bb,
        int s, int Mtot, int cshift, int offl, float* __restrict__ out) {
    extern __shared__ __align__(16) char smem[];
    int t = threadIdx.x, wid = t >> 5, lane = t & 31;
    int m0 = blockIdx.x * 128;
    int d0 = blockIdx.y * 8;

    int* sli = (int*)(smem + SM_SLI);
    int* sri = (int*)(smem + SM_SRI);
    {
        int r = m0 + t; if (r >= Mtot) r = Mtot - 1;   // clamp (level-9 partial tile)
        sli[t] = left[s + r];
        sri[t] = right[s + r];
    }

    // stage B (hi & lo): rows rr = q*8 + d  ->  global row q*128 + d0 + d
#pragma unroll
    for (int it = 0; it < 10; it++) {
        int idx = it * 128 + t;          // 1280 uint4 per buffer
        int rr = idx >> 5, w = idx & 31;
        int grow = (rr >> 3) * 128 + d0 + (rr & 7);
        *(uint4*)(smem + SM_BHI + rr * SB_B + w * 16) =
            *(const uint4*)(g_wth + grow * 256 + w * 8);
        *(uint4*)(smem + SM_BLO + rr * SB_B + w * 16) =
            *(const uint4*)(g_wtl + grow * 256 + w * 8);
    }
    __syncthreads();

    // per-thread A row byte offsets (4 rows: wid*32 + j*8 + lane>>2)
    uint32_t offL[4], offR[4];
#pragma unroll
    for (int j = 0; j < 4; j++) {
        int lm = wid * 32 + j * 8 + (lane >> 2);
        offL[j] = (uint32_t)sli[lm] * 256u;   // bytes into g_hh/g_hl
        offR[j] = (uint32_t)sri[lm] * 256u;
    }

    float acc[5][2][4];
#pragma unroll
    for (int q = 0; q < 5; q++)
#pragma unroll
        for (int rs = 0; rs < 2; rs++)
#pragma unroll
            for (int c = 0; c < 4; c++) acc[q][rs][c] = 0.f;

    const char* Hh = (const char*)g_hh;
    const char* Hl = (const char*)g_hl;
    uint32_t bbase = (uint32_t)SM_BHI + (uint32_t)(lane >> 2) * SB_B + (uint32_t)(lane & 3) * 8;

#pragma unroll
    for (int half = 0; half < 2; half++) {
        const uint32_t* offs = half ? offR : offL;
#pragma unroll
        for (int k8 = 0; k8 < 8; k8++) {
            int ks = half * 8 + k8;
            uint32_t kb = (uint32_t)k8 * 32 + (uint32_t)(lane & 3) * 4;
            uint32_t ah[2][4], al[2][4];
#pragma unroll
            for (int rs = 0; rs < 2; rs++) {
                uint32_t oa = offs[rs * 2] + kb, ob = offs[rs * 2 + 1] + kb;
                ah[rs][0] = *(const uint32_t*)(Hh + oa);
                ah[rs][1] = *(const uint32_t*)(Hh + ob);
                ah[rs][2] = *(const uint32_t*)(Hh + oa + 16);
                ah[rs][3] = *(const uint32_t*)(Hh + ob + 16);
                al[rs][0] = *(const uint32_t*)(Hl + oa);
                al[rs][1] = *(const uint32_t*)(Hl + ob);
                al[rs][2] = *(const uint32_t*)(Hl + oa + 16);
                al[rs][3] = *(const uint32_t*)(Hl + ob + 16);
            }
            uint32_t bk = bbase + (uint32_t)ks * 32;
#pragma unroll
            for (int q = 0; q < 5; q++) {
                uint32_t ba = bk + (uint32_t)q * (8 * SB_B);
                uint2 bh = *(const uint2*)(smem + ba);
                uint2 bl = *(const uint2*)(smem + ba + (SM_BLO - SM_BHI));
#pragma unroll
                for (int rs = 0; rs < 2; rs++) {
                    MMA(acc[q][rs], ah[rs], bh.x, bh.y);
                    MMA(acc[q][rs], ah[rs], bl.x, bl.y);
                    MMA(acc[q][rs], al[rs], bh.x, bh.y);
                }
            }
        }
    }

    // ---- epilogue: gates + cell update + stores (predicated on valid row)
#pragma unroll
    for (int rs = 0; rs < 2; rs++) {
#pragma unroll
        for (int g = 0; g < 2; g++) {
            int lm = wid * 32 + rs * 16 + g * 8 + (lane >> 2);
            if (m0 + lm >= Mtot) continue;
            int node = s + m0 + lm;
            int li = sli[lm], ri = sri[lm];
            int dd = d0 + (lane & 3) * 2;
            float2 cl = *(const float2*)(g_c + li * DM + dd);
            float2 cr = *(const float2*)(g_c + ri * DM + dd);
            float hv[2], cv[2];
#pragma unroll
            for (int e = 0; e < 2; e++) {
                float gi = acc[0][rs][g * 2 + e] + bb[0 * 128 + dd + e];
                float go = acc[1][rs][g * 2 + e] + bb[1 * 128 + dd + e];
                float gu = acc[2][rs][g * 2 + e] + bb[2 * 128 + dd + e];
                float gl = acc[3][rs][g * 2 + e] + bb[3 * 128 + dd + e];
                float gr = acc[4][rs][g * 2 + e] + bb[4 * 128 + dd + e];
                float clv = e ? cl.y : cl.x;
                float crv = e ? cr.y : cr.x;
                float c = sigf(gi) * tanhf(gu) + sigf(gl) * clv + sigf(gr) * crv;
                cv[e] = c;
                hv[e] = sigf(go) * tanhf(c);
            }
            *(float2*)(g_c + node * DM + dd) = make_float2(cv[0], cv[1]);
            __nv_bfloat16 h0 = __float2bfloat16(hv[0]);
            __nv_bfloat16 h1 = __float2bfloat16(hv[1]);
            __nv_bfloat162 hhp; hhp.x = h0; hhp.y = h1;
            __nv_bfloat162 hlp;
            hlp.x = __float2bfloat16(hv[0] - __bfloat162float(h0));
            hlp.y = __float2bfloat16(hv[1] - __bfloat162float(h1));
            *(__nv_bfloat162*)(g_hh + node * DM + dd) = hhp;
            *(__nv_bfloat162*)(g_hl + node * DM + dd) = hlp;
            int local = m0 + lm;
            int b = local >> cshift;
            int jj = local & ((1 << cshift) - 1);
            *(float2*)(out + ((size_t)(b * 1024 + offl + jj)) * DM + dd) =
                make_float2(hv[0], hv[1]);
        }
    }
}

// ---------------------------------------------------------------------------
// unary top level: 64 nodes, K=128, N=512 (tiny, SIMT fp32)
// ---------------------------------------------------------------------------
__global__ void unary_kernel(const int* __restrict__ left,
                             const float* __restrict__ Wu,
                             const float* __restrict__ bu,
                             float* __restrict__ out) {
    __shared__ float xh[128];
    int n = 65472 + blockIdx.x;
    int tx = threadIdx.x;
    int ch = left[n];
    xh[tx] = __bfloat162float(g_hh[ch * DM + tx]) + __bfloat162float(g_hl[ch * DM + tx]);
    __syncthreads();
    float acc[4] = {0.f, 0.f, 0.f, 0.f};
    for (int k = 0; k < 128; k++) {
        float x = xh[k];
#pragma unroll
        for (int q = 0; q < 4; q++) acc[q] += x * Wu[k * 512 + q * 128 + tx];
    }
    float cc = g_c[ch * DM + tx];
    float gi = acc[0] + bu[tx];
    float go = acc[1] + bu[128 + tx];
    float gu = acc[2] + bu[256 + tx];
    float gf = acc[3] + bu[384 + tx];
    float c = sigf(gi) * tanhf(gu) + sigf(gf) * cc;
    float h = sigf(go) * tanhf(c);
    out[((size_t)(blockIdx.x * 1024 + 1023)) * DM + tx] = h;
}

// ---------------------------------------------------------------------------
// kernel_launch: ONLY kernel launches (graph-capturable)
// ---------------------------------------------------------------------------
extern "C" void kernel_launch(void* const* d_in, const int* in_sizes, int n_in,
                              void* d_out, int out_size) {
    const int* tokens = (const int*)d_in[0];
    const int* left   = (const int*)d_in[1];
    const int* right  = (const int*)d_in[2];
    const float* emb  = (const float*)d_in[3];
    const float* Wu   = (const float*)d_in[4];
    const float* bu   = (const float*)d_in[5];
    const float* Wb   = (const float*)d_in[6];
    const float* bb   = (const float*)d_in[7];
    float* out = (float*)d_out;

    static const int Gh[10]  = {0, 32768, 49152, 57344, 61440, 63488,
                                64512, 65024, 65280, 65408};
    static const int Csh[10] = {9, 8, 7, 6, 5, 4, 3, 2, 1, 0};     // log2(C[l])
    static const int Off[10] = {0, 512, 768, 896, 960, 992, 1008, 1016, 1020, 1022};

    prep_w<<<640, 256>>>(Wb);
    leaf_kernel<<<4096, 256>>>(tokens, emb, out);
    for (int l = 1; l <= 9; l++) {
        int M = 32768 >> l;                    // 64 * C[l]; level 9 -> 64 (partial tile)
        dim3 grid((M + 127) / 128, 16);
        bin_mma<<<grid, 128, SMEM_TOT>>>(left, right, bb,
                                         Gh[l], M, Csh[l], Off[l], out);
    }
    unary_kernel<<<64, 128>>>(left, Wu, bu, out);
}